// round 1
// baseline (speedup 1.0000x reference)
#include <cuda_runtime.h>
#include <math.h>

// Problem constants (from reference): feature (4096,2048), centers (2048,2048)
#define D_K    2048
#define B_F    4096
#define C_C    2048
#define NUMR   2
#define NEARK  3
#define MAXIT  15
#define MARGINF 1.0f

// Device scratch (no allocations allowed in kernel_launch)
__device__ float g_Dfc[(size_t)B_F * C_C];   // 32 MB: squared dists feature->centers
__device__ float g_Dcc[(size_t)C_C * C_C];   // 16 MB: squared dists centers->centers
__device__ float g_fn[B_F];                  // |feature_row|^2
__device__ float g_cn[C_C];                  // |center_row|^2
__device__ int   g_near[C_C * NEARK];        // 3 nearest center indices per center (incl self)
__device__ float g_hinge[B_F];               // per-row hinge

// ---------------------------------------------------------------------------
// Row squared-norms
// ---------------------------------------------------------------------------
__global__ void row_norms_k(const float* __restrict__ A, int which /*0=feat,1=cent*/) {
    const int row = blockIdx.x;
    const int tid = threadIdx.x;
    const float* a = A + (size_t)row * D_K;
    float s = 0.f;
    for (int i = tid; i < D_K; i += 256) {
        float v = a[i];
        s = fmaf(v, v, s);
    }
    __shared__ float red[256];
    red[tid] = s;
    __syncthreads();
    for (int st = 128; st > 0; st >>= 1) {
        if (tid < st) red[tid] += red[tid + st];
        __syncthreads();
    }
    if (tid == 0) {
        if (which == 0) g_fn[row] = red[0];
        else            g_cn[row] = red[0];
    }
}

// ---------------------------------------------------------------------------
// Tiled fp32 GEMM computing D2[m][n] = a2[m] + b2[n] - 2 * (A_m . B_n)
// A: MxK row-major, B: NxK row-major. M,N multiples of 128, K multiple of 16.
// mode 0: A=feature (a2=g_fn), out=g_Dfc. mode 1: A=centers (a2=g_cn), out=g_Dcc.
// ---------------------------------------------------------------------------
#define BM 128
#define BN 128
#define BK 16

__global__ __launch_bounds__(256, 2)
void dist_gemm_k(const float* __restrict__ A, const float* __restrict__ Bm,
                 int M, int N, int mode) {
    __shared__ float As[BK][BM + 4];
    __shared__ float Bs[BK][BN + 4];

    const int tid = threadIdx.x;
    const int tx = tid & 15;       // 0..15  -> n micro-tile
    const int ty = tid >> 4;       // 0..15  -> m micro-tile
    const int bm = blockIdx.y * BM;
    const int bn = blockIdx.x * BN;

    // global load mapping: 256 threads load 128x16 tile as float4s
    const int lr = tid >> 2;          // 0..63 (row within tile, +64 for second half)
    const int lc = (tid & 3) << 2;    // 0,4,8,12 (k offset)

    const float* Aptr = A  + (size_t)(bm + lr) * D_K + lc;
    const float* Bptr = Bm + (size_t)(bn + lr) * D_K + lc;

    float acc[8][8];
#pragma unroll
    for (int i = 0; i < 8; i++)
#pragma unroll
        for (int j = 0; j < 8; j++) acc[i][j] = 0.f;

    for (int k0 = 0; k0 < D_K; k0 += BK) {
        float4 av0 = *(const float4*)(Aptr + k0);
        float4 av1 = *(const float4*)(Aptr + k0 + (size_t)64 * D_K);
        float4 bv0 = *(const float4*)(Bptr + k0);
        float4 bv1 = *(const float4*)(Bptr + k0 + (size_t)64 * D_K);

        __syncthreads();   // previous tile fully consumed
        As[lc + 0][lr] = av0.x; As[lc + 1][lr] = av0.y;
        As[lc + 2][lr] = av0.z; As[lc + 3][lr] = av0.w;
        As[lc + 0][lr + 64] = av1.x; As[lc + 1][lr + 64] = av1.y;
        As[lc + 2][lr + 64] = av1.z; As[lc + 3][lr + 64] = av1.w;
        Bs[lc + 0][lr] = bv0.x; Bs[lc + 1][lr] = bv0.y;
        Bs[lc + 2][lr] = bv0.z; Bs[lc + 3][lr] = bv0.w;
        Bs[lc + 0][lr + 64] = bv1.x; Bs[lc + 1][lr + 64] = bv1.y;
        Bs[lc + 2][lr + 64] = bv1.z; Bs[lc + 3][lr + 64] = bv1.w;
        __syncthreads();

#pragma unroll
        for (int k = 0; k < BK; k++) {
            float ar[8], br[8];
            *(float4*)&ar[0] = *(const float4*)&As[k][ty * 8];
            *(float4*)&ar[4] = *(const float4*)&As[k][ty * 8 + 4];
            *(float4*)&br[0] = *(const float4*)&Bs[k][tx * 8];
            *(float4*)&br[4] = *(const float4*)&Bs[k][tx * 8 + 4];
#pragma unroll
            for (int i = 0; i < 8; i++)
#pragma unroll
                for (int j = 0; j < 8; j++)
                    acc[i][j] = fmaf(ar[i], br[j], acc[i][j]);
        }
    }

    float*       Dout = mode ? g_Dcc : g_Dfc;
    const float* a2   = mode ? g_cn  : g_fn;
    const float* b2   = g_cn;

#pragma unroll
    for (int i = 0; i < 8; i++) {
        const int m = bm + ty * 8 + i;
        const float am = a2[m];
        const int n0 = bn + tx * 8;
        float4 o0, o1;
        o0.x = fmaf(-2.f, acc[i][0], am + b2[n0 + 0]);
        o0.y = fmaf(-2.f, acc[i][1], am + b2[n0 + 1]);
        o0.z = fmaf(-2.f, acc[i][2], am + b2[n0 + 2]);
        o0.w = fmaf(-2.f, acc[i][3], am + b2[n0 + 3]);
        o1.x = fmaf(-2.f, acc[i][4], am + b2[n0 + 4]);
        o1.y = fmaf(-2.f, acc[i][5], am + b2[n0 + 5]);
        o1.z = fmaf(-2.f, acc[i][6], am + b2[n0 + 6]);
        o1.w = fmaf(-2.f, acc[i][7], am + b2[n0 + 7]);
        *(float4*)&Dout[(size_t)m * N + n0]     = o0;
        *(float4*)&Dout[(size_t)m * N + n0 + 4] = o1;
    }
}

// ---------------------------------------------------------------------------
// Per-center 3 nearest (by squared distance, stable tie-break by index)
// ---------------------------------------------------------------------------
__global__ void near3_k() {
    const int c = blockIdx.x;
    const int tid = threadIdx.x;
    __shared__ float sd[C_C];
    __shared__ float rv[256];
    __shared__ int   ri[256];

    const float* row = g_Dcc + (size_t)c * C_C;
    for (int i = tid; i < C_C; i += 256) sd[i] = row[i];
    __syncthreads();

    for (int it = 0; it < NEARK; it++) {
        float bv = INFINITY; int bi = C_C;
        for (int i = tid; i < C_C; i += 256) {
            float v = sd[i];
            if (v < bv) { bv = v; bi = i; }   // strict <: keeps smallest index
        }
        rv[tid] = bv; ri[tid] = bi;
        __syncthreads();
        for (int st = 128; st > 0; st >>= 1) {
            if (tid < st) {
                float v2 = rv[tid + st]; int i2 = ri[tid + st];
                if (v2 < rv[tid] || (v2 == rv[tid] && i2 < ri[tid])) {
                    rv[tid] = v2; ri[tid] = i2;
                }
            }
            __syncthreads();
        }
        const int mi = ri[0];
        __syncthreads();
        if (tid == 0) {
            g_near[c * NEARK + it] = mi;
            sd[mi] = INFINITY;
        }
        __syncthreads();
    }
}

// ---------------------------------------------------------------------------
// Per-feature-row: top-15 nearest non-own centers in order; first trusted ->
// cand; hinge = max(margin + same - min_diff, 0)
// ---------------------------------------------------------------------------
__global__ void select_k() {
    const int b   = blockIdx.x;
    const int l   = b / NUMR;       // label
    const int tid = threadIdx.x;
    __shared__ float sd[C_C];
    __shared__ float rv[256];
    __shared__ int   ri[256];

    const float* row = g_Dfc + (size_t)b * C_C;
    for (int i = tid; i < C_C; i += 256) sd[i] = row[i];
    __syncthreads();
    const float same_d2 = sd[l];
    __syncthreads();
    if (tid == 0) sd[l] = INFINITY;   // mask own label
    __syncthreads();

    int found = 0;
    float cand_d2 = 0.f;
    for (int it = 0; it < MAXIT; it++) {
        float bv = INFINITY; int bi = C_C;
        for (int i = tid; i < C_C; i += 256) {
            float v = sd[i];
            if (v < bv) { bv = v; bi = i; }
        }
        rv[tid] = bv; ri[tid] = bi;
        __syncthreads();
        for (int st = 128; st > 0; st >>= 1) {
            if (tid < st) {
                float v2 = rv[tid + st]; int i2 = ri[tid + st];
                if (v2 < rv[tid] || (v2 == rv[tid] && i2 < ri[tid])) {
                    rv[tid] = v2; ri[tid] = i2;
                }
            }
            __syncthreads();
        }
        const int   mi = ri[0];
        const float mv = rv[0];
        __syncthreads();

        // trust: label l not among mi's 3 nearest centers (uniform across block)
        if (g_near[mi * NEARK + 0] != l &&
            g_near[mi * NEARK + 1] != l &&
            g_near[mi * NEARK + 2] != l) {
            found = 1;
            cand_d2 = mv;
            break;     // uniform branch: all threads agree
        }
        if (tid == 0) sd[mi] = INFINITY;
        __syncthreads();
    }

    if (tid == 0) {
        const float same = sqrtf(fmaxf(same_d2, 0.f));
        const float md   = found ? sqrtf(fmaxf(cand_d2, 0.f)) : 0.f;
        g_hinge[b] = fmaxf(MARGINF + same - md, 0.f);
    }
}

// ---------------------------------------------------------------------------
// Deterministic mean of hinges
// ---------------------------------------------------------------------------
__global__ void reduce_k(float* __restrict__ out) {
    const int tid = threadIdx.x;
    __shared__ float red[256];
    float s = 0.f;
    for (int i = tid; i < B_F; i += 256) s += g_hinge[i];
    red[tid] = s;
    __syncthreads();
    for (int st = 128; st > 0; st >>= 1) {
        if (tid < st) red[tid] += red[tid + st];
        __syncthreads();
    }
    if (tid == 0) out[0] = red[0] * (1.0f / (float)B_F);
}

// ---------------------------------------------------------------------------
extern "C" void kernel_launch(void* const* d_in, const int* in_sizes, int n_in,
                              void* d_out, int out_size) {
    (void)in_sizes; (void)n_in; (void)out_size;
    const float* feat = (const float*)d_in[0];   // (4096, 2048)
    const float* cent = (const float*)d_in[1];   // (2048, 2048)
    float* out = (float*)d_out;

    row_norms_k<<<B_F, 256>>>(feat, 0);
    row_norms_k<<<C_C, 256>>>(cent, 1);

    dim3 gfc(C_C / BN, B_F / BM);   // 16 x 32
    dim3 gcc(C_C / BN, C_C / BM);   // 16 x 16
    dist_gemm_k<<<gfc, 256>>>(feat, cent, B_F, C_C, 0);
    dist_gemm_k<<<gcc, 256>>>(cent, cent, C_C, C_C, 1);

    near3_k<<<C_C, 256>>>();
    select_k<<<B_F, 256>>>();
    reduce_k<<<1, 256>>>(out);
}